// round 12
// baseline (speedup 1.0000x reference)
#include <cuda_runtime.h>
#include <cuda_fp16.h>
#include <cstddef>
#include <cstdint>

#define N_NODES 100000
#define N_EDGES 1600000
#define DIM     128
#define DOUT    64

typedef unsigned long long u64;

// ---------------- scratch (device globals; no allocation allowed) ----------
__device__ __align__(16) float  g_bufB[(size_t)N_NODES * DIM];   // fp32 activations
__device__ __align__(16) __half g_bufH[(size_t)N_NODES * DIM];   // fp16 messages
__device__ float g_dinv[N_NODES];
__device__ int   g_deg[N_NODES];
__device__ int   g_rowstart[N_NODES];
__device__ int   g_cursor[N_NODES];
__device__ __align__(8) int2 g_csr_edge[N_EDGES];   // {src, norm bits}
__device__ int   g_total;

// ---------------- degree / normalization / CSR -----------------------------
__global__ void k_deg_zero() {
    int i = blockIdx.x * blockDim.x + threadIdx.x;
    if (i < N_NODES) g_deg[i] = 0;
    if (i == 0) g_total = 0;
}

__global__ void k_deg_count(const int* __restrict__ ei) {
    int e = blockIdx.x * blockDim.x + threadIdx.x;
    if (e < N_EDGES) atomicAdd(&g_deg[ei[N_EDGES + e]], 1);
}

// block-parallel range allocation: one atomicAdd per block; range ORDER is
// irrelevant (CSR fill order is already arbitrary). Also computes dinv.
__global__ void __launch_bounds__(1024) k_rowstart() {
    int i    = blockIdx.x * 1024 + threadIdx.x;
    int lane = threadIdx.x & 31;
    int wid  = threadIdx.x >> 5;
    int deg  = (i < N_NODES) ? g_deg[i] : 0;

    int v = deg;
#pragma unroll
    for (int off = 1; off < 32; off <<= 1) {
        int t = __shfl_up_sync(0xffffffffu, v, off);
        if (lane >= off) v += t;
    }
    __shared__ int wsum[32];
    __shared__ int base;
    if (lane == 31) wsum[wid] = v;
    __syncthreads();
    if (wid == 0) {
        int wv = wsum[lane];
#pragma unroll
        for (int off = 1; off < 32; off <<= 1) {
            int t = __shfl_up_sync(0xffffffffu, wv, off);
            if (lane >= off) wv += t;
        }
        wsum[lane] = wv;
        if (lane == 31) base = atomicAdd(&g_total, wv);
    }
    __syncthreads();
    int excl = base + (wid > 0 ? wsum[wid - 1] : 0) + v - deg;
    if (i < N_NODES) {
        g_rowstart[i] = excl;
        g_cursor[i]   = excl;
        g_dinv[i]     = rsqrtf((float)(deg + 1));   // +1 self loop
    }
}

__global__ void k_csr_fill(const int* __restrict__ ei) {
    int e = blockIdx.x * blockDim.x + threadIdx.x;
    if (e >= N_EDGES) return;
    int s = ei[e];
    int d = ei[N_EDGES + e];
    int pos = atomicAdd(&g_cursor[d], 1);
    g_csr_edge[pos] = make_int2(s, __float_as_int(g_dinv[s] * g_dinv[d]));
}

// ---------------- GEMM: Y[n,NCOL] = X[n,128] @ W[128,NCOL] (+bias) ---------
// R4 design (proven): 32-row blocks, 256 threads, f32x2 FMAs; fma pipe is the
// binder. OUT_MODE: 0 = fp32 only (fc), 1 = fp16 only (layer GEMMs).
template <int NCOL, bool BIAS, int OUT_MODE>
__global__ void __launch_bounds__(256) k_gemm(
    const float* __restrict__ X, const float* __restrict__ W,
    const float* __restrict__ bias, float* __restrict__ Y,
    __half* __restrict__ Yh, int nrows)
{
    constexpr int CG  = NCOL / 4;     // float4 column groups (32 or 16)
    constexpr int RG  = 256 / CG;     // row groups (8 or 16)
    constexpr int RPT = 32 / RG;      // rows per thread (4 or 2)

    __shared__ float Ws[64 * NCOL];
    __shared__ float Xs[32 * 68];

    const int tid  = threadIdx.x;
    const int cg   = tid % CG;
    const int rg   = tid / CG;
    const int row0 = blockIdx.x * 32;

    u64 accL[RPT], accH[RPT];
#pragma unroll
    for (int r = 0; r < RPT; ++r) { accL[r] = 0ull; accH[r] = 0ull; }

    for (int kt = 0; kt < 2; ++kt) {
        const float4* Wg  = (const float4*)(W + (size_t)kt * 64 * NCOL);
        float4*       Ws4 = (float4*)Ws;
#pragma unroll 4
        for (int i = tid; i < 64 * NCOL / 4; i += 256) Ws4[i] = Wg[i];

        for (int i = tid; i < 32 * 16; i += 256) {
            int r  = i / 16;
            int kk = i % 16;
            float4 v = make_float4(0.f, 0.f, 0.f, 0.f);
            if (row0 + r < nrows)
                v = ((const float4*)(X + (size_t)(row0 + r) * DIM + kt * 64))[kk];
            ((float4*)(Xs + r * 68))[kk] = v;
        }
        __syncthreads();

#pragma unroll 8
        for (int k = 0; k < 64; ++k) {
            ulonglong2 w = *((const ulonglong2*)(Ws + k * NCOL) + cg);
#pragma unroll
            for (int r = 0; r < RPT; ++r) {
                unsigned xu = __float_as_uint(Xs[(rg * RPT + r) * 68 + k]);
                u64 xp;
                asm("mov.b64 %0, {%1, %1};" : "=l"(xp) : "r"(xu));
                asm("fma.rn.f32x2 %0, %1, %2, %0;" : "+l"(accL[r]) : "l"(xp), "l"(w.x));
                asm("fma.rn.f32x2 %0, %1, %2, %0;" : "+l"(accH[r]) : "l"(xp), "l"(w.y));
            }
        }
        __syncthreads();
    }

#pragma unroll
    for (int r = 0; r < RPT; ++r) {
        int row = row0 + rg * RPT + r;
        if (row < nrows) {
            float2 lo, hi;
            asm("mov.b64 {%0, %1}, %2;" : "=f"(lo.x), "=f"(lo.y) : "l"(accL[r]));
            asm("mov.b64 {%0, %1}, %2;" : "=f"(hi.x), "=f"(hi.y) : "l"(accH[r]));
            float4 o = make_float4(lo.x, lo.y, hi.x, hi.y);
            if (BIAS) {
                float4 b = ((const float4*)bias)[cg];
                o.x += b.x; o.y += b.y; o.z += b.z; o.w += b.w;
            }
            if (OUT_MODE == 0) {
                ((float4*)(Y + (size_t)row * NCOL))[cg] = o;
            } else {
                __half2 h0 = __floats2half2_rn(o.x, o.y);
                __half2 h1 = __floats2half2_rn(o.z, o.w);
                uint2 pk;
                __builtin_memcpy(&pk.x, &h0, 4);
                __builtin_memcpy(&pk.y, &h1, 4);
                ((uint2*)(Yh + (size_t)row * NCOL))[cg] = pk;
            }
        }
    }
}

// fp16x2 pair -> fp32 accumulate helper
__device__ __forceinline__ void acc_h2(float4& a, uint2 r, float n) {
    __half2 h; float2 f;
    __builtin_memcpy(&h, &r.x, 4); f = __half22float2(h);
    a.x += f.x * n; a.y += f.y * n;
    __builtin_memcpy(&h, &r.y, 4); f = __half22float2(h);
    a.z += f.x * n; a.w += f.y * n;
}

// ---------------- CSR aggregation + self-loop + bias + relu ----------------
// warp per node; fp16 gathers, fp32 accumulation, fp32 output.
// Edge distribution: ONE coalesced load (lane l takes edge beg+l, covers
// deg<=32 ~ all nodes at Poisson(16)) + shfl broadcast — removes the
// edge-load leg from the L2 latency chain. Gathers at 4x unroll
// (8 in-flight 128B lines/warp, the proven L1tex footprint).
__global__ void __launch_bounds__(256) k_aggregate(
    const __half* __restrict__ Ah, float* __restrict__ B,
    const float* __restrict__ bias)
{
    int node = (blockIdx.x * 256 + threadIdx.x) >> 5;
    int lane = threadIdx.x & 31;
    if (node >= N_NODES) return;

    const uint2* AH = (const uint2*)Ah;     // 32 uint2 per 128-half row
    int beg = g_rowstart[node];
    int cnt = g_deg[node];

    // lane-parallel edge fetch: one coalesced load serves up to 32 edges
    int2 myE = make_int2(0, 0);
    if (lane < cnt) myE = g_csr_edge[beg + lane];

    float4 acc0 = make_float4(0.f, 0.f, 0.f, 0.f);
    float4 acc1 = make_float4(0.f, 0.f, 0.f, 0.f);

    const int m = cnt < 32 ? cnt : 32;
    int j = 0;
    for (; j + 4 <= m; j += 4) {
        int   s0 = __shfl_sync(0xffffffffu, myE.x, j + 0);
        int   s1 = __shfl_sync(0xffffffffu, myE.x, j + 1);
        int   s2 = __shfl_sync(0xffffffffu, myE.x, j + 2);
        int   s3 = __shfl_sync(0xffffffffu, myE.x, j + 3);
        float n0 = __int_as_float(__shfl_sync(0xffffffffu, myE.y, j + 0));
        float n1 = __int_as_float(__shfl_sync(0xffffffffu, myE.y, j + 1));
        float n2 = __int_as_float(__shfl_sync(0xffffffffu, myE.y, j + 2));
        float n3 = __int_as_float(__shfl_sync(0xffffffffu, myE.y, j + 3));
        uint2 r0 = AH[(size_t)s0 * 32 + lane];
        uint2 r1 = AH[(size_t)s1 * 32 + lane];
        uint2 r2 = AH[(size_t)s2 * 32 + lane];
        uint2 r3 = AH[(size_t)s3 * 32 + lane];
        acc_h2(acc0, r0, n0);
        acc_h2(acc1, r1, n1);
        acc_h2(acc0, r2, n2);
        acc_h2(acc1, r3, n3);
    }
    for (; j < m; ++j) {
        int   s0 = __shfl_sync(0xffffffffu, myE.x, j);
        float n0 = __int_as_float(__shfl_sync(0xffffffffu, myE.y, j));
        uint2 r0 = AH[(size_t)s0 * 32 + lane];
        acc_h2(acc0, r0, n0);
    }
    // rare fallback: deg > 32 (broadcast loads)
    for (j = 32; j < cnt; ++j) {
        int2 e0 = g_csr_edge[beg + j];
        uint2 r0 = AH[(size_t)e0.x * 32 + lane];
        acc_h2(acc0, r0, __int_as_float(e0.y));
    }

    float di = g_dinv[node];
    float sn = di * di;
    uint2 sr = AH[(size_t)node * 32 + lane];
    acc_h2(acc1, sr, sn);                       // self loop from fp16 row
    float4 bb = ((const float4*)bias)[lane];
    float4 o;
    o.x = fmaxf(acc0.x + acc1.x + bb.x, 0.f);
    o.y = fmaxf(acc0.y + acc1.y + bb.y, 0.f);
    o.z = fmaxf(acc0.z + acc1.z + bb.z, 0.f);
    o.w = fmaxf(acc0.w + acc1.w + bb.w, 0.f);
    ((float4*)(B + (size_t)node * DIM))[lane] = o;
}

// ---------------- launch ----------------------------------------------------
extern "C" void kernel_launch(void* const* d_in, const int* in_sizes, int n_in,
                              void* d_out, int out_size)
{
    const float* x    = (const float*)d_in[0];
    const int*   ei   = (const int*)d_in[1];     // int32 (JAX x64 disabled)
    const float* W1   = (const float*)d_in[2];
    const float* b1   = (const float*)d_in[3];
    const float* W2   = (const float*)d_in[4];
    const float* b2   = (const float*)d_in[5];
    const float* fcW  = (const float*)d_in[6];
    const float* fcb  = (const float*)d_in[7];
    float*       out  = (float*)d_out;

    void *pB_, *pH_;
    cudaGetSymbolAddress(&pB_, g_bufB);
    cudaGetSymbolAddress(&pH_, g_bufH);
    float*  bufB = (float*)pB_;
    __half* bufH = (__half*)pH_;

    const int TB = 256;
    const int gN  = (N_NODES + TB - 1) / TB;
    const int gE  = (N_EDGES + TB - 1) / TB;
    const int gG  = (N_NODES + 31) / 32;            // 32-row gemm tiles
    const int gAg = (N_NODES * 32 + TB - 1) / TB;   // warp per node
    const int gRS = (N_NODES + 1023) / 1024;

    // fork a side stream: CSR precompute concurrent with GEMM1 (small but free)
    cudaStream_t sCsr;
    cudaStreamCreateWithFlags(&sCsr, cudaStreamNonBlocking);
    cudaEvent_t evFork, evCsrDone;
    cudaEventCreateWithFlags(&evFork,    cudaEventDisableTiming);
    cudaEventCreateWithFlags(&evCsrDone, cudaEventDisableTiming);

    cudaEventRecord(evFork, 0);
    cudaStreamWaitEvent(sCsr, evFork, 0);

    // CSR precompute chain (side stream)
    k_deg_zero<<<gN, TB, 0, sCsr>>>();
    k_deg_count<<<gE, TB, 0, sCsr>>>(ei);
    k_rowstart<<<gRS, 1024, 0, sCsr>>>();
    k_csr_fill<<<gE, TB, 0, sCsr>>>(ei);
    cudaEventRecord(evCsrDone, sCsr);

    // GEMM1 (main stream, concurrent with CSR build)
    k_gemm<DIM, false, 1><<<gG, TB>>>(x, W1, nullptr, nullptr, bufH, N_NODES);

    // join: aggregate1 needs both GEMM1 output and CSR
    cudaStreamWaitEvent(0, evCsrDone, 0);
    k_aggregate<<<gAg, TB>>>(bufH, bufB, b1);

    // layer 2
    k_gemm<DIM, false, 1><<<gG, TB>>>(bufB, W2, nullptr, nullptr, bufH, N_NODES);
    k_aggregate<<<gAg, TB>>>(bufH, bufB, b2);

    // fc (fp32 exact)
    k_gemm<DOUT, true, 0><<<gG, TB>>>(bufB, fcW, fcb, out, nullptr, N_NODES);

    cudaEventDestroy(evFork);
    cudaEventDestroy(evCsrDone);
    cudaStreamDestroy(sCsr);
}

// round 13
// speedup vs baseline: 1.0655x; 1.0655x over previous
#include <cuda_runtime.h>
#include <cuda_fp16.h>
#include <cstddef>
#include <cstdint>

#define N_NODES 100000
#define N_EDGES 1600000
#define DIM     128
#define DOUT    64

typedef unsigned long long u64;

// ---------------- scratch (device globals; no allocation allowed) ----------
__device__ __align__(16) float  g_bufB[(size_t)N_NODES * DIM];   // fp32 activations
__device__ __align__(16) __half g_bufH[(size_t)N_NODES * DIM];   // fp16 msgs (pre-scaled by dinv[src])
__device__ float g_dinv[N_NODES];
__device__ int   g_deg[N_NODES];
__device__ int   g_rowstart[N_NODES];
__device__ int   g_cursor[N_NODES];
__device__ int   g_csr_src[N_EDGES];    // src only (norm factored out)
__device__ int   g_total;

// ---------------- degree / normalization / CSR -----------------------------
__global__ void k_deg_zero() {
    int i = blockIdx.x * blockDim.x + threadIdx.x;
    if (i < N_NODES) g_deg[i] = 0;
    if (i == 0) g_total = 0;
}

__global__ void k_deg_count(const int* __restrict__ ei) {
    int e = blockIdx.x * blockDim.x + threadIdx.x;
    if (e < N_EDGES) atomicAdd(&g_deg[ei[N_EDGES + e]], 1);
}

// block-parallel range allocation: one atomicAdd per block; range ORDER is
// irrelevant (CSR fill order is already arbitrary). Also computes dinv.
__global__ void __launch_bounds__(1024) k_rowstart() {
    int i    = blockIdx.x * 1024 + threadIdx.x;
    int lane = threadIdx.x & 31;
    int wid  = threadIdx.x >> 5;
    int deg  = (i < N_NODES) ? g_deg[i] : 0;

    int v = deg;
#pragma unroll
    for (int off = 1; off < 32; off <<= 1) {
        int t = __shfl_up_sync(0xffffffffu, v, off);
        if (lane >= off) v += t;
    }
    __shared__ int wsum[32];
    __shared__ int base;
    if (lane == 31) wsum[wid] = v;
    __syncthreads();
    if (wid == 0) {
        int wv = wsum[lane];
#pragma unroll
        for (int off = 1; off < 32; off <<= 1) {
            int t = __shfl_up_sync(0xffffffffu, wv, off);
            if (lane >= off) wv += t;
        }
        wsum[lane] = wv;
        if (lane == 31) base = atomicAdd(&g_total, wv);
    }
    __syncthreads();
    int excl = base + (wid > 0 ? wsum[wid - 1] : 0) + v - deg;
    if (i < N_NODES) {
        g_rowstart[i] = excl;
        g_cursor[i]   = excl;
        g_dinv[i]     = rsqrtf((float)(deg + 1));   // +1 self loop
    }
}

__global__ void k_csr_fill(const int* __restrict__ ei) {
    int e = blockIdx.x * blockDim.x + threadIdx.x;
    if (e >= N_EDGES) return;
    int s = ei[e];
    int d = ei[N_EDGES + e];
    int pos = atomicAdd(&g_cursor[d], 1);
    g_csr_src[pos] = s;
}

// ---------------- GEMM: Y[n,NCOL] = X[n,128] @ W[128,NCOL] (+bias) ---------
// R4 design (proven): 32-row blocks, 256 threads, f32x2 FMAs; fma pipe is the
// binder. OUT_MODE: 0 = fp32 (fc), 1 = fp16 messages pre-scaled by dinv[row].
template <int NCOL, bool BIAS, int OUT_MODE>
__global__ void __launch_bounds__(256) k_gemm(
    const float* __restrict__ X, const float* __restrict__ W,
    const float* __restrict__ bias, float* __restrict__ Y,
    __half* __restrict__ Yh, int nrows)
{
    constexpr int CG  = NCOL / 4;     // float4 column groups (32 or 16)
    constexpr int RG  = 256 / CG;     // row groups (8 or 16)
    constexpr int RPT = 32 / RG;      // rows per thread (4 or 2)

    __shared__ float Ws[64 * NCOL];
    __shared__ float Xs[32 * 68];

    const int tid  = threadIdx.x;
    const int cg   = tid % CG;
    const int rg   = tid / CG;
    const int row0 = blockIdx.x * 32;

    u64 accL[RPT], accH[RPT];
#pragma unroll
    for (int r = 0; r < RPT; ++r) { accL[r] = 0ull; accH[r] = 0ull; }

    for (int kt = 0; kt < 2; ++kt) {
        const float4* Wg  = (const float4*)(W + (size_t)kt * 64 * NCOL);
        float4*       Ws4 = (float4*)Ws;
#pragma unroll 4
        for (int i = tid; i < 64 * NCOL / 4; i += 256) Ws4[i] = Wg[i];

        for (int i = tid; i < 32 * 16; i += 256) {
            int r  = i / 16;
            int kk = i % 16;
            float4 v = make_float4(0.f, 0.f, 0.f, 0.f);
            if (row0 + r < nrows)
                v = ((const float4*)(X + (size_t)(row0 + r) * DIM + kt * 64))[kk];
            ((float4*)(Xs + r * 68))[kk] = v;
        }
        __syncthreads();

#pragma unroll 8
        for (int k = 0; k < 64; ++k) {
            ulonglong2 w = *((const ulonglong2*)(Ws + k * NCOL) + cg);
#pragma unroll
            for (int r = 0; r < RPT; ++r) {
                unsigned xu = __float_as_uint(Xs[(rg * RPT + r) * 68 + k]);
                u64 xp;
                asm("mov.b64 %0, {%1, %1};" : "=l"(xp) : "r"(xu));
                asm("fma.rn.f32x2 %0, %1, %2, %0;" : "+l"(accL[r]) : "l"(xp), "l"(w.x));
                asm("fma.rn.f32x2 %0, %1, %2, %0;" : "+l"(accH[r]) : "l"(xp), "l"(w.y));
            }
        }
        __syncthreads();
    }

#pragma unroll
    for (int r = 0; r < RPT; ++r) {
        int row = row0 + rg * RPT + r;
        if (row < nrows) {
            float2 lo, hi;
            asm("mov.b64 {%0, %1}, %2;" : "=f"(lo.x), "=f"(lo.y) : "l"(accL[r]));
            asm("mov.b64 {%0, %1}, %2;" : "=f"(hi.x), "=f"(hi.y) : "l"(accH[r]));
            float4 o = make_float4(lo.x, lo.y, hi.x, hi.y);
            if (BIAS) {
                float4 b = ((const float4*)bias)[cg];
                o.x += b.x; o.y += b.y; o.z += b.z; o.w += b.w;
            }
            if (OUT_MODE == 0) {
                ((float4*)(Y + (size_t)row * NCOL))[cg] = o;
            } else {
                float dv = g_dinv[row];
                __half2 h0 = __floats2half2_rn(o.x * dv, o.y * dv);
                __half2 h1 = __floats2half2_rn(o.z * dv, o.w * dv);
                uint2 pk;
                __builtin_memcpy(&pk.x, &h0, 4);
                __builtin_memcpy(&pk.y, &h1, 4);
                ((uint2*)(Yh + (size_t)row * NCOL))[cg] = pk;
            }
        }
    }
}

// fp16x2 pair -> fp32 add (messages are pre-scaled; no multiply needed)
__device__ __forceinline__ void add_h2(float4& a, uint2 r) {
    __half2 h; float2 f;
    __builtin_memcpy(&h, &r.x, 4); f = __half22float2(h);
    a.x += f.x; a.y += f.y;
    __builtin_memcpy(&h, &r.y, 4); f = __half22float2(h);
    a.z += f.x; a.w += f.y;
}

// ---------------- CSR aggregation + self-loop + bias + relu ----------------
// warp per node; fp16 gathers of pre-scaled messages, fp32 accumulation;
// out = (sum + msg[node]) * dinv[node] + bias, relu. 4x unroll on fp16 =
// 8 in-flight 128B lines/warp (proven L1tex footprint). Broadcast edge
// loads are L1-resident and cheap — do NOT shfl-ify (R12 regression).
__global__ void __launch_bounds__(256) k_aggregate(
    const __half* __restrict__ Ah, float* __restrict__ B,
    const float* __restrict__ bias)
{
    int node = (blockIdx.x * 256 + threadIdx.x) >> 5;
    int lane = threadIdx.x & 31;
    if (node >= N_NODES) return;

    const uint2* AH = (const uint2*)Ah;     // 32 uint2 per 128-half row
    int beg = g_rowstart[node];
    int cnt = g_deg[node];

    float4 acc0 = make_float4(0.f, 0.f, 0.f, 0.f);
    float4 acc1 = make_float4(0.f, 0.f, 0.f, 0.f);

    int j = 0;
    for (; j + 4 <= cnt; j += 4) {
        int s0 = g_csr_src[beg + j + 0];
        int s1 = g_csr_src[beg + j + 1];
        int s2 = g_csr_src[beg + j + 2];
        int s3 = g_csr_src[beg + j + 3];
        uint2 r0 = AH[(size_t)s0 * 32 + lane];
        uint2 r1 = AH[(size_t)s1 * 32 + lane];
        uint2 r2 = AH[(size_t)s2 * 32 + lane];
        uint2 r3 = AH[(size_t)s3 * 32 + lane];
        add_h2(acc0, r0);
        add_h2(acc1, r1);
        add_h2(acc0, r2);
        add_h2(acc1, r3);
    }
    for (; j < cnt; ++j) {
        uint2 r0 = AH[(size_t)g_csr_src[beg + j] * 32 + lane];
        add_h2(acc0, r0);
    }

    uint2 sr = AH[(size_t)node * 32 + lane];
    add_h2(acc1, sr);                        // self loop (msg[node]=h*dinv)
    float dv = g_dinv[node];
    float4 bb = ((const float4*)bias)[lane];
    float4 o;
    o.x = fmaxf((acc0.x + acc1.x) * dv + bb.x, 0.f);
    o.y = fmaxf((acc0.y + acc1.y) * dv + bb.y, 0.f);
    o.z = fmaxf((acc0.z + acc1.z) * dv + bb.z, 0.f);
    o.w = fmaxf((acc0.w + acc1.w) * dv + bb.w, 0.f);
    ((float4*)(B + (size_t)node * DIM))[lane] = o;
}

// ---------------- launch ----------------------------------------------------
extern "C" void kernel_launch(void* const* d_in, const int* in_sizes, int n_in,
                              void* d_out, int out_size)
{
    const float* x    = (const float*)d_in[0];
    const int*   ei   = (const int*)d_in[1];     // int32 (JAX x64 disabled)
    const float* W1   = (const float*)d_in[2];
    const float* b1   = (const float*)d_in[3];
    const float* W2   = (const float*)d_in[4];
    const float* b2   = (const float*)d_in[5];
    const float* fcW  = (const float*)d_in[6];
    const float* fcb  = (const float*)d_in[7];
    float*       out  = (float*)d_out;

    void *pB_, *pH_;
    cudaGetSymbolAddress(&pB_, g_bufB);
    cudaGetSymbolAddress(&pH_, g_bufH);
    float*  bufB = (float*)pB_;
    __half* bufH = (__half*)pH_;

    const int TB = 256;
    const int gN  = (N_NODES + TB - 1) / TB;
    const int gE  = (N_EDGES + TB - 1) / TB;
    const int gG  = (N_NODES + 31) / 32;            // 32-row gemm tiles
    const int gAg = (N_NODES * 32 + TB - 1) / TB;   // warp per node
    const int gRS = (N_NODES + 1023) / 1024;

    // deg/dinv chain must precede GEMM1 (epilogue scales by dinv)
    k_deg_zero<<<gN, TB>>>();
    k_deg_count<<<gE, TB>>>(ei);
    k_rowstart<<<gRS, 1024>>>();

    // csr_fill overlaps GEMM1 (independent of it)
    cudaStream_t sCsr;
    cudaStreamCreateWithFlags(&sCsr, cudaStreamNonBlocking);
    cudaEvent_t evFork, evCsrDone;
    cudaEventCreateWithFlags(&evFork,    cudaEventDisableTiming);
    cudaEventCreateWithFlags(&evCsrDone, cudaEventDisableTiming);

    cudaEventRecord(evFork, 0);
    cudaStreamWaitEvent(sCsr, evFork, 0);
    k_csr_fill<<<gE, TB, 0, sCsr>>>(ei);
    cudaEventRecord(evCsrDone, sCsr);

    // layer 1
    k_gemm<DIM, false, 1><<<gG, TB>>>(x, W1, nullptr, nullptr, bufH, N_NODES);
    cudaStreamWaitEvent(0, evCsrDone, 0);
    k_aggregate<<<gAg, TB>>>(bufH, bufB, b1);

    // layer 2
    k_gemm<DIM, false, 1><<<gG, TB>>>(bufB, W2, nullptr, nullptr, bufH, N_NODES);
    k_aggregate<<<gAg, TB>>>(bufH, bufB, b2);

    // fc (fp32 exact)
    k_gemm<DOUT, true, 0><<<gG, TB>>>(bufB, fcW, fcb, out, nullptr, N_NODES);

    cudaEventDestroy(evFork);
    cudaEventDestroy(evCsrDone);
    cudaStreamDestroy(sCsr);
}